// round 1
// baseline (speedup 1.0000x reference)
#include <cuda_runtime.h>
#include <math_constants.h>

// Soft cross entropy, n x k (k = 512 fixed by problem), fp32 inputs.
// loss_i = (m_i + lse_i) * sum(t_i) - sum(t_i * x_i); output = mean_i loss_i.
//
// Warp-per-row streaming kernel: each warp loads its 512-float row as
// 4 float4 per lane (coalesced, stride 32*16B), does shuffle reductions
// for max and sum(exp), then streams the target row accumulating
// sum(t) and sum(t*x). Double-precision global accumulator for the mean.

__device__ double g_acc;

__global__ void zero_acc_kernel() { g_acc = 0.0; }

__device__ __forceinline__ float warp_max(float v) {
#pragma unroll
    for (int o = 16; o > 0; o >>= 1)
        v = fmaxf(v, __shfl_xor_sync(0xFFFFFFFFu, v, o));
    return v;
}

__device__ __forceinline__ float warp_sum(float v) {
#pragma unroll
    for (int o = 16; o > 0; o >>= 1)
        v += __shfl_xor_sync(0xFFFFFFFFu, v, o);
    return v;
}

__global__ __launch_bounds__(256) void sce_kernel(
    const float* __restrict__ input,
    const float* __restrict__ target,
    int nrows)
{
    constexpr int K = 512;
    constexpr int F4_PER_LANE = K / 4 / 32;  // 4

    __shared__ double s_block_acc;
    if (threadIdx.x == 0) s_block_acc = 0.0;
    __syncthreads();

    const int warp_in_block = threadIdx.x >> 5;
    const int lane = threadIdx.x & 31;
    const long long row = (long long)blockIdx.x * (blockDim.x >> 5) + warp_in_block;

    if (row < nrows) {
        const float4* __restrict__ xin =
            reinterpret_cast<const float4*>(input + row * (long long)K);
        const float4* __restrict__ tin =
            reinterpret_cast<const float4*>(target + row * (long long)K);

        float4 x[F4_PER_LANE];
#pragma unroll
        for (int i = 0; i < F4_PER_LANE; i++)
            x[i] = xin[lane + 32 * i];

        // Row max
        float m = -CUDART_INF_F;
#pragma unroll
        for (int i = 0; i < F4_PER_LANE; i++) {
            m = fmaxf(m, fmaxf(fmaxf(x[i].x, x[i].y), fmaxf(x[i].z, x[i].w)));
        }
        m = warp_max(m);

        // Sum exp(x - m)
        float se = 0.0f;
#pragma unroll
        for (int i = 0; i < F4_PER_LANE; i++) {
            se += __expf(x[i].x - m);
            se += __expf(x[i].y - m);
            se += __expf(x[i].z - m);
            se += __expf(x[i].w - m);
        }
        se = warp_sum(se);
        const float lse = m + logf(se);

        // Stream target: sum(t) and sum(t*x)
        float tsum = 0.0f, txsum = 0.0f;
#pragma unroll
        for (int i = 0; i < F4_PER_LANE; i++) {
            float4 t = tin[lane + 32 * i];
            tsum += (t.x + t.y) + (t.z + t.w);
            txsum = fmaf(t.x, x[i].x, txsum);
            txsum = fmaf(t.y, x[i].y, txsum);
            txsum = fmaf(t.z, x[i].z, txsum);
            txsum = fmaf(t.w, x[i].w, txsum);
        }
        tsum = warp_sum(tsum);
        txsum = warp_sum(txsum);

        if (lane == 0) {
            float loss = fmaf(lse, tsum, -txsum);
            atomicAdd(&s_block_acc, (double)loss);
        }
    }

    __syncthreads();
    if (threadIdx.x == 0) {
        atomicAdd(&g_acc, s_block_acc);
    }
}

__global__ void finalize_kernel(float* out, int nrows) {
    out[0] = (float)(g_acc / (double)nrows);
}

extern "C" void kernel_launch(void* const* d_in, const int* in_sizes, int n_in,
                              void* d_out, int out_size)
{
    const float* input  = (const float*)d_in[0];
    const float* target = (const float*)d_in[1];
    float* out = (float*)d_out;

    const int K = 512;
    const int nrows = in_sizes[0] / K;

    zero_acc_kernel<<<1, 1>>>();

    const int warps_per_block = 8;
    const int threads = warps_per_block * 32;
    const int blocks = (nrows + warps_per_block - 1) / warps_per_block;
    sce_kernel<<<blocks, threads>>>(input, target, nrows);

    finalize_kernel<<<1, 1>>>(out, nrows);
}

// round 2
// speedup vs baseline: 1.0046x; 1.0046x over previous
#include <cuda_runtime.h>
#include <math_constants.h>

// Soft cross entropy, n x k (k = 512), fp32 inputs.
// loss_i = (m_i + lse_i) * sum(t_i) - sum(t_i * x_i); output = mean_i loss_i.
//
// Single-kernel version: warp-per-row streaming, block-level double
// accumulation, and last-block finalization via ticket counter.
// The last block reads-and-resets the global accumulator with atomicExch,
// making the kernel deterministic across CUDA-graph replays.

__device__ double g_acc;            // statically zero-initialized
__device__ unsigned int g_count;    // statically zero-initialized

__device__ __forceinline__ float warp_max(float v) {
#pragma unroll
    for (int o = 16; o > 0; o >>= 1)
        v = fmaxf(v, __shfl_xor_sync(0xFFFFFFFFu, v, o));
    return v;
}

__device__ __forceinline__ float warp_sum(float v) {
#pragma unroll
    for (int o = 16; o > 0; o >>= 1)
        v += __shfl_xor_sync(0xFFFFFFFFu, v, o);
    return v;
}

__global__ __launch_bounds__(256) void sce_kernel(
    const float* __restrict__ input,
    const float* __restrict__ target,
    float* __restrict__ out,
    int nrows)
{
    constexpr int K = 512;
    constexpr int F4_PER_LANE = K / 4 / 32;  // 4

    __shared__ double s_block_acc;
    if (threadIdx.x == 0) s_block_acc = 0.0;
    __syncthreads();

    const int warp_in_block = threadIdx.x >> 5;
    const int lane = threadIdx.x & 31;
    const long long row = (long long)blockIdx.x * (blockDim.x >> 5) + warp_in_block;

    if (row < nrows) {
        const float4* __restrict__ xin =
            reinterpret_cast<const float4*>(input + row * (long long)K);
        const float4* __restrict__ tin =
            reinterpret_cast<const float4*>(target + row * (long long)K);

        // Front-batch all 8 streaming loads (MLP_p1 = 8, evict-first).
        float4 x[F4_PER_LANE];
        float4 t[F4_PER_LANE];
#pragma unroll
        for (int i = 0; i < F4_PER_LANE; i++)
            x[i] = __ldcs(&xin[lane + 32 * i]);
#pragma unroll
        for (int i = 0; i < F4_PER_LANE; i++)
            t[i] = __ldcs(&tin[lane + 32 * i]);

        // Row max
        float m = -CUDART_INF_F;
#pragma unroll
        for (int i = 0; i < F4_PER_LANE; i++)
            m = fmaxf(m, fmaxf(fmaxf(x[i].x, x[i].y), fmaxf(x[i].z, x[i].w)));
        m = warp_max(m);

        // Sum exp(x - m), plus sum(t) and sum(t*x)
        float se = 0.0f, tsum = 0.0f, txsum = 0.0f;
#pragma unroll
        for (int i = 0; i < F4_PER_LANE; i++) {
            se += __expf(x[i].x - m);
            se += __expf(x[i].y - m);
            se += __expf(x[i].z - m);
            se += __expf(x[i].w - m);
            tsum += (t[i].x + t[i].y) + (t[i].z + t[i].w);
            txsum = fmaf(t[i].x, x[i].x, txsum);
            txsum = fmaf(t[i].y, x[i].y, txsum);
            txsum = fmaf(t[i].z, x[i].z, txsum);
            txsum = fmaf(t[i].w, x[i].w, txsum);
        }
        se = warp_sum(se);
        tsum = warp_sum(tsum);
        txsum = warp_sum(txsum);

        if (lane == 0) {
            const float lse = m + logf(se);
            float loss = fmaf(lse, tsum, -txsum);
            atomicAdd(&s_block_acc, (double)loss);
        }
    }

    __syncthreads();
    if (threadIdx.x == 0) {
        atomicAdd(&g_acc, s_block_acc);
        __threadfence();
        unsigned int ticket = atomicAdd(&g_count, 1u);
        if (ticket == gridDim.x - 1) {
            // Last block: read-and-reset accumulator, write result,
            // reset counter for the next graph replay.
            unsigned long long raw =
                atomicExch(reinterpret_cast<unsigned long long*>(&g_acc), 0ull);
            double total = __longlong_as_double((long long)raw);
            out[0] = (float)(total / (double)nrows);
            g_count = 0u;
            __threadfence();
        }
    }
}

extern "C" void kernel_launch(void* const* d_in, const int* in_sizes, int n_in,
                              void* d_out, int out_size)
{
    const float* input  = (const float*)d_in[0];
    const float* target = (const float*)d_in[1];
    float* out = (float*)d_out;

    const int K = 512;
    const int nrows = in_sizes[0] / K;

    const int warps_per_block = 8;
    const int threads = warps_per_block * 32;
    const int blocks = (nrows + warps_per_block - 1) / warps_per_block;
    sce_kernel<<<blocks, threads>>>(input, target, out, nrows);
}